// round 15
// baseline (speedup 1.0000x reference)
#include <cuda_runtime.h>
#include <math.h>

// Problem constants
#define BB   8
#define NN   1024
#define CC   1024
#define HH   16
#define HD   64
#define NTASKS 10
#define NFRQ   3000
#define ROWS (BB*NN)          // 8192
#define QKVC (3*CC)           // 3072
#define PL   (CC*CC)          // one 1024x1024 plane

// Scratch (device globals: allocation-free). hi/lo = tf32 split planes.
__device__ float g_qkv  [ROWS*QKVC];   // 96 MB
__device__ float g_dcth [PL],      g_dctl [PL];
__device__ float g_S    [2*PL];                       // plain [Sk;Sv]
__device__ float g_Sh   [2*PL],    g_Sl   [2*PL];
__device__ float g_tmp2h[2*PL],    g_tmp2l[2*PL];
__device__ float g_W    [2*PL];                       // plain [Wk|Wv]
__device__ float g_Weffh[3*PL],    g_Weffl[3*PL];
__device__ float g_xh   [8*PL],    g_xl   [8*PL];
__device__ float g_ctxh [8*PL],    g_ctxl [8*PL];
__device__ float g_Wph  [PL],      g_Wpl  [PL];

// ---------------------------------------------------------------------------
__device__ __forceinline__ unsigned f2tf32(float f) {
    unsigned u; asm("cvt.rna.tf32.f32 %0, %1;" : "=r"(u) : "f"(f)); return u;
}
__device__ __forceinline__ void split_tf32(float v, float& hi, float& lo) {
    hi = __uint_as_float(f2tf32(v));
    lo = __uint_as_float(f2tf32(v - hi));
}

__global__ void zero_S_kernel() {
    int i = blockIdx.x * blockDim.x + threadIdx.x;
    if (i < 2*PL) g_S[i] = 0.f;
}

__global__ void scatter_kernel(const float* __restrict__ coef_k,
                               const float* __restrict__ coef_v,
                               const int*   __restrict__ indices,
                               const int*   __restrict__ task) {
    int i = blockIdx.x * blockDim.x + threadIdx.x;
    if (i >= NTASKS * NFRQ) return;
    int t = i / NFRQ;
    if (t > *task) return;
    int idx = indices[i];
    atomicAdd(&g_S[idx],      coef_k[i]);
    atomicAdd(&g_S[PL + idx], coef_v[i]);
}

// Generic split: src -> (dst_h, dst_l) tf32 planes.
__global__ void split_kernel(const float* __restrict__ src,
                             float* __restrict__ dh, float* __restrict__ dl,
                             int n) {
    int i = blockIdx.x * blockDim.x + threadIdx.x;
    if (i >= n) return;
    float h, l; split_tf32(src[i], h, l);
    dh[i] = h; dl[i] = l;
}

// Orthonormal DCT-II matrix (split output); fp32 angle math replicates jax.
__global__ void dct_kernel() {
    int idx = blockIdx.x * blockDim.x + threadIdx.x;
    if (idx >= PL) return;
    int i = idx >> 10, j = idx & 1023;
    float v;
    if (i == 0) {
        v = 0.03125f;
    } else {
        const float pif = 3.14159265358979323846f;
        float ang = pif * (float)i;
        ang = ang * (float)(2*j + 1);
        ang = ang / 2048.0f;
        float c = (float)cos((double)ang);
        v = (float)sqrt(2.0/1024.0) * c;
    }
    float h, l; split_tf32(v, h, l);
    g_dcth[idx] = h; g_dctl[idx] = l;
}

// W_eff = Wqkv + [0; Wk; Wv], written as split planes.
__global__ void add_weights_kernel(const float* __restrict__ Wqkv) {
    int i = blockIdx.x * blockDim.x + threadIdx.x;
    if (i >= QKVC*CC) return;
    float v = Wqkv[i];
    int row = i >> 10;
    if (row >= 2*CC)      v += g_W[PL + i - 2*PL];   // Wv
    else if (row >= CC)   v += g_W[i - PL];          // Wk
    float h, l; split_tf32(v, h, l);
    g_Weffh[i] = h; g_Weffl[i] = l;
}

// ---------------------------------------------------------------------------
// 3xTF32 GEMM on pre-split operands: C = op(A)@op(B) (+bias), where
// A = Ah+Al, B = Bh+Bl (tf32 planes); acc += Ah·Bh + Ah·Bl + Al·Bh.
// NO per-fragment ALU splits — pure LDS + mma inner loop.
// Block tile 64x64x16, 4 warps (warp tile 32x32), 2-stage cp.async, 5 CTA/SM.
//   TRANSA=0: a(m,k)=A[m*lda+k]   TRANSA=1: a(m,k)=A[k*lda+m]
//   TRANSB=1: b(k,n)=B[n*ldb+k]   TRANSB=0: b(k,n)=B[k*ldb+n]
// SPLIT_OUT: write C split into (Ch, Cl) planes; else plain into Ch.
// M,N multiples of 64; K multiple of 16. blockIdx.z: B += z*zsB, C += z*zsC.

__device__ __forceinline__ void mma8(float* d, const unsigned* a,
                                     unsigned b0, unsigned b1) {
    asm volatile(
        "mma.sync.aligned.m16n8k8.row.col.f32.tf32.tf32.f32 "
        "{%0,%1,%2,%3}, {%4,%5,%6,%7}, {%8,%9}, {%0,%1,%2,%3};\n"
        : "+f"(d[0]), "+f"(d[1]), "+f"(d[2]), "+f"(d[3])
        : "r"(a[0]), "r"(a[1]), "r"(a[2]), "r"(a[3]), "r"(b0), "r"(b1));
}

__device__ __forceinline__ void cp_async16(void* smem_dst, const void* gmem_src) {
    unsigned saddr = (unsigned)__cvta_generic_to_shared(smem_dst);
    asm volatile("cp.async.ca.shared.global [%0], [%1], 16;\n"
                 :: "r"(saddr), "l"(gmem_src));
}
__device__ __forceinline__ void cp_commit() {
    asm volatile("cp.async.commit_group;\n");
}

template<int TRANSA, int TRANSB, int SPLIT_OUT>
__global__ __launch_bounds__(128, 5)
void mma_gemm3x(int M, int N, int K,
                const float* __restrict__ Ah, const float* __restrict__ Al, int lda,
                const float* __restrict__ Bh, const float* __restrict__ Bl, int ldb,
                float* __restrict__ Ch, float* __restrict__ Cl, int ldc,
                size_t zsB, size_t zsC, const float* __restrict__ bias) {
    // Stride 20 rows: fragment LDS banks (20*lg+lt) mod 32 all distinct.
    __shared__ float Ash[2][64][20], Asl[2][64][20];
    __shared__ float Bsh[2][64][20], Bsl[2][64][20];   // 40 KB total

    Bh += (size_t)blockIdx.z * zsB;  Bl += (size_t)blockIdx.z * zsB;
    Ch += (size_t)blockIdx.z * zsC;
    if (SPLIT_OUT) Cl += (size_t)blockIdx.z * zsC;

    const int t    = threadIdx.x;
    const int lane = t & 31;
    const int wid  = t >> 5;          // 0..3
    const int wr   = wid & 1;         // warp m-index -> 32 rows
    const int wc   = wid >> 1;        // warp n-index -> 32 cols
    const int m0   = blockIdx.y * 64;
    const int n0   = blockIdx.x * 64;
    const int lg   = lane >> 2;       // 0..7
    const int lt   = lane & 3;        // 0..3

    float acc[2][4][4];
    #pragma unroll
    for (int i = 0; i < 2; i++)
        #pragma unroll
        for (int j = 0; j < 4; j++)
            #pragma unroll
            for (int r = 0; r < 4; r++) acc[i][j][r] = 0.f;

    // Stage 64x16 A (h+l) and 64x16 B (h+l) into slot st.
    auto stage = [&](int st, int k0) {
        if (!TRANSA) {
            #pragma unroll
            for (int it = 0; it < 2; it++) {
                int idx = it * 128 + t;              // 256 float4 per plane
                int m = idx >> 2, kc = (idx & 3) * 4;
                size_t g = (size_t)(m0 + m) * lda + k0 + kc;
                cp_async16(&Ash[st][m][kc], Ah + g);
                cp_async16(&Asl[st][m][kc], Al + g);
            }
        } else {
            #pragma unroll
            for (int it = 0; it < 2; it++) {
                int idx = it * 128 + t;
                int k = idx >> 4, mc = (idx & 15) * 4;
                size_t g = (size_t)(k0 + k) * lda + m0 + mc;
                float4 vh = *(const float4*)(Ah + g);
                float4 vl = *(const float4*)(Al + g);
                Ash[st][mc+0][k] = vh.x; Ash[st][mc+1][k] = vh.y;
                Ash[st][mc+2][k] = vh.z; Ash[st][mc+3][k] = vh.w;
                Asl[st][mc+0][k] = vl.x; Asl[st][mc+1][k] = vl.y;
                Asl[st][mc+2][k] = vl.z; Asl[st][mc+3][k] = vl.w;
            }
        }
        if (TRANSB) {
            #pragma unroll
            for (int it = 0; it < 2; it++) {
                int idx = it * 128 + t;
                int n = idx >> 2, kc = (idx & 3) * 4;
                size_t g = (size_t)(n0 + n) * ldb + k0 + kc;
                cp_async16(&Bsh[st][n][kc], Bh + g);
                cp_async16(&Bsl[st][n][kc], Bl + g);
            }
        } else {
            #pragma unroll
            for (int it = 0; it < 2; it++) {
                int idx = it * 128 + t;
                int k = idx >> 4, nc = (idx & 15) * 4;
                size_t g = (size_t)(k0 + k) * ldb + n0 + nc;
                float4 vh = *(const float4*)(Bh + g);
                float4 vl = *(const float4*)(Bl + g);
                Bsh[st][nc+0][k] = vh.x; Bsh[st][nc+1][k] = vh.y;
                Bsh[st][nc+2][k] = vh.z; Bsh[st][nc+3][k] = vh.w;
                Bsl[st][nc+0][k] = vl.x; Bsl[st][nc+1][k] = vl.y;
                Bsl[st][nc+2][k] = vl.z; Bsl[st][nc+3][k] = vl.w;
            }
        }
        cp_commit();
    };

    const int niter = K >> 4;
    stage(0, 0);

    for (int it = 0; it < niter; it++) {
        const int cur = it & 1;
        asm volatile("cp.async.wait_group 0;\n");   // chunk it arrived
        __syncthreads();                            // data visible; prev compute done
        if (it + 1 < niter) stage(cur ^ 1, (it + 1) << 4);  // overlaps compute below

        #pragma unroll
        for (int ks = 0; ks < 2; ks++) {
            const int c = ks * 8 + lt;
            unsigned ah[2][4], al[2][4];
            #pragma unroll
            for (int ms = 0; ms < 2; ms++) {
                int r = wr * 32 + ms * 16 + lg;
                ah[ms][0] = __float_as_uint(Ash[cur][r    ][c    ]);
                ah[ms][1] = __float_as_uint(Ash[cur][r + 8][c    ]);
                ah[ms][2] = __float_as_uint(Ash[cur][r    ][c + 4]);
                ah[ms][3] = __float_as_uint(Ash[cur][r + 8][c + 4]);
                al[ms][0] = __float_as_uint(Asl[cur][r    ][c    ]);
                al[ms][1] = __float_as_uint(Asl[cur][r + 8][c    ]);
                al[ms][2] = __float_as_uint(Asl[cur][r    ][c + 4]);
                al[ms][3] = __float_as_uint(Asl[cur][r + 8][c + 4]);
            }
            #pragma unroll
            for (int ns = 0; ns < 4; ns++) {
                int n = wc * 32 + ns * 8 + lg;
                unsigned b0h = __float_as_uint(Bsh[cur][n][c    ]);
                unsigned b1h = __float_as_uint(Bsh[cur][n][c + 4]);
                unsigned b0l = __float_as_uint(Bsl[cur][n][c    ]);
                unsigned b1l = __float_as_uint(Bsl[cur][n][c + 4]);
                #pragma unroll
                for (int ms = 0; ms < 2; ms++) {
                    mma8(acc[ms][ns], ah[ms], b0h, b1h);  // hi*hi
                    mma8(acc[ms][ns], ah[ms], b0l, b1l);  // hi*lo
                    mma8(acc[ms][ns], al[ms], b0h, b1h);  // lo*hi
                }
            }
        }
    }

    // ---- epilogue ----
    #pragma unroll
    for (int ms = 0; ms < 2; ms++) {
        #pragma unroll
        for (int ns = 0; ns < 4; ns++) {
            int row = m0 + wr * 32 + ms * 16 + lg;
            int col = n0 + wc * 32 + ns * 8 + 2 * lt;
            float b0 = bias ? bias[col] : 0.f;
            float b1 = bias ? bias[col + 1] : 0.f;
            size_t o0 = (size_t)row * ldc + col;
            size_t o1 = (size_t)(row + 8) * ldc + col;
            float v0 = acc[ms][ns][0] + b0, v1 = acc[ms][ns][1] + b1;
            float v2 = acc[ms][ns][2] + b0, v3 = acc[ms][ns][3] + b1;
            if (SPLIT_OUT) {
                float h, l;
                split_tf32(v0, h, l); Ch[o0]   = h; Cl[o0]   = l;
                split_tf32(v1, h, l); Ch[o0+1] = h; Cl[o0+1] = l;
                split_tf32(v2, h, l); Ch[o1]   = h; Cl[o1]   = l;
                split_tf32(v3, h, l); Ch[o1+1] = h; Cl[o1+1] = l;
            } else {
                Ch[o0] = v0; Ch[o0 + 1] = v1;
                Ch[o1] = v2; Ch[o1 + 1] = v3;
            }
        }
    }
}

// ---------------------------------------------------------------------------
// Packed f32x2 helpers (sm_103a FFMA2 — per-lane rounding identical to fmaf)
__device__ __forceinline__ unsigned long long pack2(float lo, float hi) {
    unsigned long long r;
    asm("mov.b64 %0, {%1, %2};" : "=l"(r) : "f"(lo), "f"(hi));
    return r;
}
__device__ __forceinline__ void unpack2(unsigned long long v, float& lo, float& hi) {
    asm("mov.b64 {%0, %1}, %2;" : "=f"(lo), "=f"(hi) : "l"(v));
}
__device__ __forceinline__ void fma2(unsigned long long& d,
                                     unsigned long long a, unsigned long long b) {
    asm("fma.rn.f32x2 %0, %1, %2, %3;" : "=l"(d) : "l"(a), "l"(b), "l"(d));
}
__device__ __forceinline__ void mul2(unsigned long long& d,
                                     unsigned long long a, unsigned long long b) {
    asm("mul.rn.f32x2 %0, %1, %2;" : "=l"(d) : "l"(a), "l"(b));
}

// Flash-style attention; writes ctx as split tf32 planes for the proj GEMM.
__global__ __launch_bounds__(64)
void attn_kernel() {
    __shared__ float Ks[64][68];
    __shared__ float Vs[64][68];
    const int tid = threadIdx.x;
    const int bh  = blockIdx.y;
    const int b = bh >> 4, h = bh & 15;
    const int n = blockIdx.x * 64 + tid;

    const float* qrow = g_qkv + (size_t)(b * NN + n) * QKVC + h * HD;
    unsigned long long qv[32];
    #pragma unroll
    for (int d4 = 0; d4 < 16; d4++) {
        float4 q4 = *(const float4*)(qrow + d4 * 4);
        qv[d4*2+0] = pack2(q4.x * 0.125f, q4.y * 0.125f);
        qv[d4*2+1] = pack2(q4.z * 0.125f, q4.w * 0.125f);
    }

    float m_run = -INFINITY, l_run = 0.f;
    unsigned long long acc[32];
    #pragma unroll
    for (int j = 0; j < 32; j++) acc[j] = 0ull;

    for (int kt = 0; kt < NN / 64; kt++) {
        const float* krow = g_qkv + (size_t)(b * NN + kt * 64 + tid) * QKVC + CC  + h * HD;
        const float* vrow = g_qkv + (size_t)(b * NN + kt * 64 + tid) * QKVC + 2*CC + h * HD;
        #pragma unroll
        for (int d4 = 0; d4 < 16; d4++) {
            *(float4*)&Ks[tid][d4 * 4] = *(const float4*)(krow + d4 * 4);
            *(float4*)&Vs[tid][d4 * 4] = *(const float4*)(vrow + d4 * 4);
        }
        __syncthreads();

        for (int kk = 0; kk < 64; kk++) {
            unsigned long long s2 = 0ull;
            const unsigned long long* k2 = (const unsigned long long*)&Ks[kk][0];
            #pragma unroll
            for (int j = 0; j < 32; j++) fma2(s2, qv[j], k2[j]);
            float slo, shi; unpack2(s2, slo, shi);
            float s = slo + shi;

            if (s > m_run) {
                float corr = expf(m_run - s);
                l_run *= corr;
                unsigned long long c2 = pack2(corr, corr);
                #pragma unroll
                for (int j = 0; j < 32; j++) mul2(acc[j], acc[j], c2);
                m_run = s;
            }
            float p = expf(s - m_run);
            l_run += p;
            unsigned long long p2 = pack2(p, p);
            const unsigned long long* v2 = (const unsigned long long*)&Vs[kk][0];
            #pragma unroll
            for (int j = 0; j < 32; j++) fma2(acc[j], p2, v2[j]);
        }
        __syncthreads();
    }

    float inv = 1.f / l_run;
    size_t obase = (size_t)(b * NN + n) * CC + h * HD;
    #pragma unroll
    for (int j = 0; j < 32; j++) {
        float a0, a1;
        unpack2(acc[j], a0, a1);
        float h0, l0, h1, l1;
        split_tf32(a0 * inv, h0, l0);
        split_tf32(a1 * inv, h1, l1);
        g_ctxh[obase + j*2]     = h0;  g_ctxl[obase + j*2]     = l0;
        g_ctxh[obase + j*2 + 1] = h1;  g_ctxl[obase + j*2 + 1] = l1;
    }
}

// ---------------------------------------------------------------------------
extern "C" void kernel_launch(void* const* d_in, const int* in_sizes, int n_in,
                              void* d_out, int out_size) {
    const float* x     = (const float*)d_in[0];
    const float* Wqkv  = (const float*)d_in[1];
    const float* Wproj = (const float*)d_in[2];
    const float* bproj = (const float*)d_in[3];
    const float* coefk = (const float*)d_in[4];
    const float* coefv = (const float*)d_in[5];
    const int*   indices = (const int*)d_in[6];
    const int*   task  = (const int*)d_in[7];
    float*       out   = (float*)d_out;
    (void)in_sizes; (void)n_in; (void)out_size;

    void *p;
    cudaGetSymbolAddress(&p, g_qkv);   float* qkv   = (float*)p;
    cudaGetSymbolAddress(&p, g_dcth);  float* dcth  = (float*)p;
    cudaGetSymbolAddress(&p, g_dctl);  float* dctl  = (float*)p;
    cudaGetSymbolAddress(&p, g_S);     float* S     = (float*)p;
    cudaGetSymbolAddress(&p, g_Sh);    float* Sh    = (float*)p;
    cudaGetSymbolAddress(&p, g_Sl);    float* Sl    = (float*)p;
    cudaGetSymbolAddress(&p, g_tmp2h); float* tmp2h = (float*)p;
    cudaGetSymbolAddress(&p, g_tmp2l); float* tmp2l = (float*)p;
    cudaGetSymbolAddress(&p, g_W);     float* W     = (float*)p;
    cudaGetSymbolAddress(&p, g_Weffh); float* Weffh = (float*)p;
    cudaGetSymbolAddress(&p, g_Weffl); float* Weffl = (float*)p;
    cudaGetSymbolAddress(&p, g_xh);    float* xh    = (float*)p;
    cudaGetSymbolAddress(&p, g_xl);    float* xl    = (float*)p;
    cudaGetSymbolAddress(&p, g_ctxh);  float* ctxh  = (float*)p;
    cudaGetSymbolAddress(&p, g_ctxl);  float* ctxl  = (float*)p;
    cudaGetSymbolAddress(&p, g_Wph);   float* Wph   = (float*)p;
    cudaGetSymbolAddress(&p, g_Wpl);   float* Wpl   = (float*)p;

    // 1. Input pre-splits (independent of DCT chain)
    split_kernel<<<(8*PL + 255)/256, 256>>>(x, xh, xl, 8*PL);
    split_kernel<<<(PL + 255)/256, 256>>>(Wproj, Wph, Wpl, PL);

    // 2. DCT-LoRA weights
    zero_S_kernel<<<(2*PL + 255)/256, 256>>>();
    scatter_kernel<<<(NTASKS*NFRQ + 255)/256, 256>>>(coefk, coefv, indices, task);
    dct_kernel<<<(PL + 255)/256, 256>>>();
    split_kernel<<<(2*PL + 255)/256, 256>>>(S, Sh, Sl, 2*PL);

    // stage 1: tmp2(2048x1024) = [Sk;Sv] @ Bm   (split output)
    mma_gemm3x<0,0,1><<<dim3(16,32,1), 128>>>(
        2*CC, CC, CC, Sh, Sl, CC, dcth, dctl, CC, tmp2h, tmp2l, CC, 0, 0, nullptr);
    // stage 2 (batched z): W{k,v} = Bm^T @ tmp2{k,v}   (plain output)
    mma_gemm3x<1,0,0><<<dim3(16,16,2), 128>>>(
        CC, CC, CC, dcth, dctl, CC, tmp2h, tmp2l, CC, W, nullptr, CC,
        (size_t)PL, (size_t)PL, nullptr);

    // 3. W_eff = Wqkv + [0; Wk; Wv]  (split output)
    add_weights_kernel<<<(QKVC*CC + 255)/256, 256>>>(Wqkv);

    // 4. qkv = x @ W_eff^T
    mma_gemm3x<0,1,0><<<dim3(QKVC/64, ROWS/64, 1), 128>>>(
        ROWS, QKVC, CC, xh, xl, CC, Weffh, Weffl, CC, qkv, nullptr, QKVC,
        0, 0, nullptr);

    // 5. attention -> ctx (split output)
    attn_kernel<<<dim3(NN/64, BB*HH), 64>>>();

    // 6. out = ctx @ Wproj^T + b
    mma_gemm3x<0,1,0><<<dim3(16, ROWS/64, 1), 128>>>(
        ROWS, CC, CC, ctxh, ctxl, CC, Wph, Wpl, CC, out, nullptr, CC,
        0, 0, bproj);
}

// round 16
// speedup vs baseline: 1.2937x; 1.2937x over previous
#include <cuda_runtime.h>
#include <math.h>

// Problem constants
#define BB   8
#define NN   1024
#define CC   1024
#define HH   16
#define HD   64
#define NTASKS 10
#define NFRQ   3000
#define ROWS (BB*NN)          // 8192
#define QKVC (3*CC)           // 3072

// Scratch (device globals: allocation-free)
__device__ float g_qkv [ROWS*QKVC];    // 96 MB  (q|k|v column blocks)
__device__ float g_dct [CC*CC];        // 4 MB
__device__ float g_S   [2*CC*CC];      // 8 MB  stacked scatter planes [Sk;Sv]
__device__ float g_tmp2[2*CC*CC];      // 8 MB  stacked stage-1 out
__device__ float g_W   [2*CC*CC];      // 8 MB  [Wk | Wv]
__device__ float g_Weff[QKVC*CC];      // 12 MB fused qkv+LoRA weight
__device__ float g_ctx [ROWS*CC];      // 32 MB

// ---------------------------------------------------------------------------
__global__ void zero_S_kernel() {
    int i = blockIdx.x * blockDim.x + threadIdx.x;
    if (i < 2*CC*CC) g_S[i] = 0.f;
}

__global__ void scatter_kernel(const float* __restrict__ coef_k,
                               const float* __restrict__ coef_v,
                               const int*   __restrict__ indices,
                               const int*   __restrict__ task) {
    int i = blockIdx.x * blockDim.x + threadIdx.x;
    if (i >= NTASKS * NFRQ) return;
    int t = i / NFRQ;
    if (t > *task) return;
    int idx = indices[i];
    atomicAdd(&g_S[idx],         coef_k[i]);
    atomicAdd(&g_S[CC*CC + idx], coef_v[i]);
}

// Orthonormal DCT-II matrix; fp32 angle arithmetic replicates jax exactly.
__global__ void dct_kernel() {
    int idx = blockIdx.x * blockDim.x + threadIdx.x;
    if (idx >= CC*CC) return;
    int i = idx >> 10, j = idx & 1023;
    float v;
    if (i == 0) {
        v = 0.03125f;
    } else {
        const float pif = 3.14159265358979323846f;
        float ang = pif * (float)i;
        ang = ang * (float)(2*j + 1);
        ang = ang / 2048.0f;
        float c = (float)cos((double)ang);
        v = (float)sqrt(2.0/1024.0) * c;
    }
    g_dct[idx] = v;
}

// W_eff = Wqkv, with row blocks [1024:2048) += Wk, [2048:3072) += Wv.
__global__ void add_weights_kernel(const float* __restrict__ Wqkv) {
    int i = blockIdx.x * blockDim.x + threadIdx.x;
    if (i >= QKVC*CC) return;
    float v = Wqkv[i];
    int row = i >> 10;
    if (row >= 2*CC)      v += g_W[CC*CC + i - 2*CC*CC];   // Wv
    else if (row >= CC)   v += g_W[i - CC*CC];             // Wk
    g_Weff[i] = v;
}

// ---------------------------------------------------------------------------
// 3xTF32 tensor-core GEMM, 3-stage cp.async pipeline, single sync/chunk.
// Block tile 128x64x16, 8 warps (warp tile 32x32), mma.sync m16n8k8 tf32.
// fp32-accurate: Dekker mask-split in registers —
//   hi = v & 0xFFFFE000 (exact tf32 truncation, 1 LOP)
//   lo = v - hi         (exact FSUB; HW truncates lo's low mantissa in mma)
// hh accumulates into acc; hl+lh into accL (breaks HMMA RAW chains);
// merged at epilogue. blockIdx.z batching: B += z*zsB, C += z*zsC.
//   TRANSA=0: a(m,k)=A[m*lda+k]   TRANSA=1: a(m,k)=A[k*lda+m]
//   TRANSB=1: b(k,n)=B[n*ldb+k]   TRANSB=0: b(k,n)=B[k*ldb+n]
// M multiple of 128; N multiple of 64; K multiple of 16.

__device__ __forceinline__ void split_mask(float v, unsigned& hi, unsigned& lo) {
    unsigned h = __float_as_uint(v) & 0xFFFFE000u;
    hi = h;
    lo = __float_as_uint(v - __uint_as_float(h));
}

__device__ __forceinline__ void mma8(float* d, const unsigned* a,
                                     unsigned b0, unsigned b1) {
    asm volatile(
        "mma.sync.aligned.m16n8k8.row.col.f32.tf32.tf32.f32 "
        "{%0,%1,%2,%3}, {%4,%5,%6,%7}, {%8,%9}, {%0,%1,%2,%3};\n"
        : "+f"(d[0]), "+f"(d[1]), "+f"(d[2]), "+f"(d[3])
        : "r"(a[0]), "r"(a[1]), "r"(a[2]), "r"(a[3]), "r"(b0), "r"(b1));
}

__device__ __forceinline__ void cp_async16(void* smem_dst, const void* gmem_src) {
    unsigned saddr = (unsigned)__cvta_generic_to_shared(smem_dst);
    asm volatile("cp.async.ca.shared.global [%0], [%1], 16;\n"
                 :: "r"(saddr), "l"(gmem_src));
}
__device__ __forceinline__ void cp_commit() {
    asm volatile("cp.async.commit_group;\n");
}

template<int TRANSA, int TRANSB>
__global__ __launch_bounds__(256, 2)
void mma_gemm3x(int M, int N, int K,
                const float* __restrict__ A, int lda,
                const float* __restrict__ B, int ldb,
                float* __restrict__ C, int ldc,
                size_t zsB, size_t zsC,
                int accumulate, const float* __restrict__ bias) {
    // Raw fp32 tiles, 3 pipeline slots. Row stride 20 -> conflict-free frags.
    __shared__ float Asm[3][128][20];
    __shared__ float Bsm[3][64][20];

    B += (size_t)blockIdx.z * zsB;
    C += (size_t)blockIdx.z * zsC;

    const int t    = threadIdx.x;
    const int lane = t & 31;
    const int wid  = t >> 5;
    const int wr   = wid & 3;          // warp m-index (0..3) -> 32 rows
    const int wc   = wid >> 2;         // warp n-index (0..1) -> 32 cols
    const int m0   = blockIdx.y * 128;
    const int n0   = blockIdx.x * 64;
    const int lg   = lane >> 2;        // 0..7
    const int lt   = lane & 3;         // 0..3

    float acc [2][4][4];   // hi*hi terms
    float accL[2][4][4];   // hi*lo + lo*hi terms (independent RAW chain)
    #pragma unroll
    for (int i = 0; i < 2; i++)
        #pragma unroll
        for (int j = 0; j < 4; j++)
            #pragma unroll
            for (int r = 0; r < 4; r++) { acc[i][j][r] = 0.f; accL[i][j][r] = 0.f; }

    // Stage one 128x16 A tile + 64x16 B tile into slot st.
    auto stage = [&](int st, int k0) {
        if (!TRANSA) {
            #pragma unroll
            for (int it = 0; it < 2; it++) {
                int idx = it * 256 + t;                  // 512 float4
                int m = idx >> 2, kc = (idx & 3) * 4;
                cp_async16(&Asm[st][m][kc],
                           A + (size_t)(m0 + m) * lda + k0 + kc);
            }
        } else {
            #pragma unroll
            for (int it = 0; it < 2; it++) {
                int idx = it * 256 + t;
                int k = idx >> 5, mc = (idx & 31) * 4;
                float4 v = *(const float4*)(A + (size_t)(k0 + k) * lda + m0 + mc);
                Asm[st][mc+0][k] = v.x; Asm[st][mc+1][k] = v.y;
                Asm[st][mc+2][k] = v.z; Asm[st][mc+3][k] = v.w;
            }
        }
        if (TRANSB) {
            int idx = t;                                 // 256 float4
            int n = idx >> 2, kc = (idx & 3) * 4;
            cp_async16(&Bsm[st][n][kc],
                       B + (size_t)(n0 + n) * ldb + k0 + kc);
        } else {
            int idx = t;
            int k = idx >> 4, nc = (idx & 15) * 4;
            float4 v = *(const float4*)(B + (size_t)(k0 + k) * ldb + n0 + nc);
            Bsm[st][nc+0][k] = v.x; Bsm[st][nc+1][k] = v.y;
            Bsm[st][nc+2][k] = v.z; Bsm[st][nc+3][k] = v.w;
        }
        cp_commit();
    };

    const int niter = K >> 4;
    stage(0, 0);
    if (niter > 1) stage(1, 16);

    for (int it = 0; it < niter; it++) {
        const int cur = it % 3;
        if (it + 1 < niter) asm volatile("cp.async.wait_group 1;\n");
        else                asm volatile("cp.async.wait_group 0;\n");
        __syncthreads();   // slot (it-1)%3 free; data of chunk it visible
        if (it + 2 < niter) stage((it + 2) % 3, (it + 2) << 4);

        // ---- compute on slot cur: 2 k-steps of m16n8k8 ----
        #pragma unroll
        for (int ks = 0; ks < 2; ks++) {
            const int c = ks * 8 + lt;
            unsigned ah[2][4], al[2][4];
            #pragma unroll
            for (int ms = 0; ms < 2; ms++) {
                int r = wr * 32 + ms * 16 + lg;
                split_mask(Asm[cur][r    ][c    ], ah[ms][0], al[ms][0]);
                split_mask(Asm[cur][r + 8][c    ], ah[ms][1], al[ms][1]);
                split_mask(Asm[cur][r    ][c + 4], ah[ms][2], al[ms][2]);
                split_mask(Asm[cur][r + 8][c + 4], ah[ms][3], al[ms][3]);
            }
            #pragma unroll
            for (int ns = 0; ns < 4; ns++) {
                int n = wc * 32 + ns * 8 + lg;
                unsigned b0h, b0l, b1h, b1l;
                split_mask(Bsm[cur][n][c    ], b0h, b0l);
                split_mask(Bsm[cur][n][c + 4], b1h, b1l);
                #pragma unroll
                for (int ms = 0; ms < 2; ms++) {
                    mma8(acc [ms][ns], ah[ms], b0h, b1h);  // hi*hi
                    mma8(accL[ms][ns], ah[ms], b0l, b1l);  // hi*lo
                    mma8(accL[ms][ns], al[ms], b0h, b1h);  // lo*hi
                }
            }
        }
    }

    // ---- epilogue (merge hi and lo accumulators) ----
    #pragma unroll
    for (int ms = 0; ms < 2; ms++) {
        #pragma unroll
        for (int ns = 0; ns < 4; ns++) {
            int row = m0 + wr * 32 + ms * 16 + lg;
            int col = n0 + wc * 32 + ns * 8 + 2 * lt;
            float b0 = bias ? bias[col] : 0.f;
            float b1 = bias ? bias[col + 1] : 0.f;
            size_t o0 = (size_t)row * ldc + col;
            size_t o1 = (size_t)(row + 8) * ldc + col;
            float v0 = acc[ms][ns][0] + accL[ms][ns][0] + b0;
            float v1 = acc[ms][ns][1] + accL[ms][ns][1] + b1;
            float v2 = acc[ms][ns][2] + accL[ms][ns][2] + b0;
            float v3 = acc[ms][ns][3] + accL[ms][ns][3] + b1;
            if (accumulate) {
                v0 += C[o0]; v1 += C[o0 + 1];
                v2 += C[o1]; v3 += C[o1 + 1];
            }
            C[o0] = v0; C[o0 + 1] = v1;
            C[o1] = v2; C[o1 + 1] = v3;
        }
    }
}

// ---------------------------------------------------------------------------
// Packed f32x2 helpers (sm_103a FFMA2 — per-lane rounding identical to fmaf)
__device__ __forceinline__ unsigned long long pack2(float lo, float hi) {
    unsigned long long r;
    asm("mov.b64 %0, {%1, %2};" : "=l"(r) : "f"(lo), "f"(hi));
    return r;
}
__device__ __forceinline__ void unpack2(unsigned long long v, float& lo, float& hi) {
    asm("mov.b64 {%0, %1}, %2;" : "=f"(lo), "=f"(hi) : "l"(v));
}
__device__ __forceinline__ void fma2(unsigned long long& d,
                                     unsigned long long a, unsigned long long b) {
    asm("fma.rn.f32x2 %0, %1, %2, %3;" : "=l"(d) : "l"(a), "l"(b), "l"(d));
}
__device__ __forceinline__ void mul2(unsigned long long& d,
                                     unsigned long long a, unsigned long long b) {
    asm("mul.rn.f32x2 %0, %1, %2;" : "=l"(d) : "l"(a), "l"(b));
}

// Flash-style attention (fp32, packed f32x2 math). One block = 64 queries of
// one (b,h); each thread owns one query row.
__global__ __launch_bounds__(64)
void attn_kernel() {
    __shared__ float Ks[64][68];
    __shared__ float Vs[64][68];
    const int tid = threadIdx.x;
    const int bh  = blockIdx.y;
    const int b = bh >> 4, h = bh & 15;
    const int n = blockIdx.x * 64 + tid;

    const float* qrow = g_qkv + (size_t)(b * NN + n) * QKVC + h * HD;
    unsigned long long qv[32];          // 64 dims as 32 pairs (scaled)
    #pragma unroll
    for (int d4 = 0; d4 < 16; d4++) {
        float4 q4 = *(const float4*)(qrow + d4 * 4);
        qv[d4*2+0] = pack2(q4.x * 0.125f, q4.y * 0.125f);
        qv[d4*2+1] = pack2(q4.z * 0.125f, q4.w * 0.125f);
    }

    float m_run = -INFINITY, l_run = 0.f;
    unsigned long long acc[32];
    #pragma unroll
    for (int j = 0; j < 32; j++) acc[j] = 0ull;

    for (int kt = 0; kt < NN / 64; kt++) {
        const float* krow = g_qkv + (size_t)(b * NN + kt * 64 + tid) * QKVC + CC  + h * HD;
        const float* vrow = g_qkv + (size_t)(b * NN + kt * 64 + tid) * QKVC + 2*CC + h * HD;
        #pragma unroll
        for (int d4 = 0; d4 < 16; d4++) {
            *(float4*)&Ks[tid][d4 * 4] = *(const float4*)(krow + d4 * 4);
            *(float4*)&Vs[tid][d4 * 4] = *(const float4*)(vrow + d4 * 4);
        }
        __syncthreads();

        for (int kk = 0; kk < 64; kk++) {
            unsigned long long s2 = 0ull;
            const unsigned long long* k2 = (const unsigned long long*)&Ks[kk][0];
            #pragma unroll
            for (int j = 0; j < 32; j++) fma2(s2, qv[j], k2[j]);
            float slo, shi; unpack2(s2, slo, shi);
            float s = slo + shi;

            if (s > m_run) {
                float corr = expf(m_run - s);   // expf(-inf)=0 handles init
                l_run *= corr;
                unsigned long long c2 = pack2(corr, corr);
                #pragma unroll
                for (int j = 0; j < 32; j++) mul2(acc[j], acc[j], c2);
                m_run = s;
            }
            float p = expf(s - m_run);
            l_run += p;
            unsigned long long p2 = pack2(p, p);
            const unsigned long long* v2 = (const unsigned long long*)&Vs[kk][0];
            #pragma unroll
            for (int j = 0; j < 32; j++) fma2(acc[j], p2, v2[j]);
        }
        __syncthreads();
    }

    float inv = 1.f / l_run;
    float* orow = g_ctx + (size_t)(b * NN + n) * CC + h * HD;
    #pragma unroll
    for (int j = 0; j < 16; j++) {
        float a0, a1, a2, a3;
        unpack2(acc[j*2+0], a0, a1);
        unpack2(acc[j*2+1], a2, a3);
        float4 o4;
        o4.x = a0 * inv; o4.y = a1 * inv;
        o4.z = a2 * inv; o4.w = a3 * inv;
        *(float4*)(orow + j * 4) = o4;
    }
}

// ---------------------------------------------------------------------------
extern "C" void kernel_launch(void* const* d_in, const int* in_sizes, int n_in,
                              void* d_out, int out_size) {
    const float* x     = (const float*)d_in[0];
    const float* Wqkv  = (const float*)d_in[1];
    const float* Wproj = (const float*)d_in[2];
    const float* bproj = (const float*)d_in[3];
    const float* coefk = (const float*)d_in[4];
    const float* coefv = (const float*)d_in[5];
    const int*   indices = (const int*)d_in[6];
    const int*   task  = (const int*)d_in[7];
    float*       out   = (float*)d_out;
    (void)in_sizes; (void)n_in; (void)out_size;

    void *p;
    cudaGetSymbolAddress(&p, g_qkv);  float* qkv  = (float*)p;
    cudaGetSymbolAddress(&p, g_dct);  float* dct  = (float*)p;
    cudaGetSymbolAddress(&p, g_S);    float* S    = (float*)p;
    cudaGetSymbolAddress(&p, g_tmp2); float* tmp2 = (float*)p;
    cudaGetSymbolAddress(&p, g_W);    float* W    = (float*)p;
    cudaGetSymbolAddress(&p, g_Weff); float* Weff = (float*)p;
    cudaGetSymbolAddress(&p, g_ctx);  float* ctx  = (float*)p;

    const size_t PLsz = (size_t)CC * CC;   // one 1024x1024 plane

    // 1. DCT-LoRA weights
    zero_S_kernel<<<(2*CC*CC + 255)/256, 256>>>();
    scatter_kernel<<<(NTASKS*NFRQ + 255)/256, 256>>>(coefk, coefv, indices, task);
    dct_kernel<<<(CC*CC + 255)/256, 256>>>();

    // stage 1 (batched rows): tmp2(2048x1024) = [Sk;Sv] @ Bm
    mma_gemm3x<0,0><<<dim3(16,16,1), 256>>>(
        2*CC, CC, CC, S, CC, dct, CC, tmp2, CC, 0, 0, 0, nullptr);
    // stage 2 (batched z): W{k,v} = Bm^T @ tmp2{k,v}
    mma_gemm3x<1,0><<<dim3(16,8,2), 256>>>(
        CC, CC, CC, dct, CC, tmp2, CC, W, CC, PLsz, PLsz, 0, nullptr);

    // 2. Fuse LoRA weights into qkv weight: W_eff = Wqkv + [0; Wk; Wv]
    add_weights_kernel<<<(QKVC*CC + 255)/256, 256>>>(Wqkv);

    // 3. qkv = x @ W_eff^T  (k/v LoRA adds folded in — one GEMM)
    mma_gemm3x<0,1><<<dim3(QKVC/64, ROWS/128), 256>>>(
        ROWS, QKVC, CC, x, CC, Weff, CC, qkv, QKVC, 0, 0, 0, nullptr);

    // 4. attention -> ctx
    attn_kernel<<<dim3(NN/64, BB*HH), 64>>>();

    // 5. out = ctx @ Wproj^T + b
    mma_gemm3x<0,1><<<dim3(16, ROWS/128), 256>>>(
        ROWS, CC, CC, ctx, CC, Wproj, CC, out, CC, 0, 0, 0, bproj);
}

// round 17
// speedup vs baseline: 1.2947x; 1.0008x over previous
#include <cuda_runtime.h>
#include <math.h>

// Problem constants
#define BB   8
#define NN   1024
#define CC   1024
#define HH   16
#define HD   64
#define NTASKS 10
#define NFRQ   3000
#define ROWS (BB*NN)          // 8192
#define QKVC (3*CC)           // 3072

// Scratch (device globals: allocation-free)
__device__ float g_qkv [ROWS*QKVC];    // 96 MB  (q|k|v column blocks)
__device__ float g_dct [CC*CC];        // 4 MB
__device__ float g_S   [2*CC*CC];      // 8 MB  stacked scatter planes [Sk;Sv]
__device__ float g_tmp2[2*CC*CC];      // 8 MB  stacked stage-1 out
__device__ float g_W   [2*CC*CC];      // 8 MB  [Wk | Wv]
__device__ float g_Weff[QKVC*CC];      // 12 MB fused qkv+LoRA weight
__device__ float g_ctx [ROWS*CC];      // 32 MB

// ---------------------------------------------------------------------------
__global__ void zero_S_kernel() {
    int i = blockIdx.x * blockDim.x + threadIdx.x;
    if (i < 2*CC*CC) g_S[i] = 0.f;
}

__global__ void scatter_kernel(const float* __restrict__ coef_k,
                               const float* __restrict__ coef_v,
                               const int*   __restrict__ indices,
                               const int*   __restrict__ task) {
    int i = blockIdx.x * blockDim.x + threadIdx.x;
    if (i >= NTASKS * NFRQ) return;
    int t = i / NFRQ;
    if (t > *task) return;
    int idx = indices[i];
    atomicAdd(&g_S[idx],         coef_k[i]);
    atomicAdd(&g_S[CC*CC + idx], coef_v[i]);
}

// Orthonormal DCT-II matrix; fp32 angle arithmetic replicates jax exactly.
__global__ void dct_kernel() {
    int idx = blockIdx.x * blockDim.x + threadIdx.x;
    if (idx >= CC*CC) return;
    int i = idx >> 10, j = idx & 1023;
    float v;
    if (i == 0) {
        v = 0.03125f;
    } else {
        const float pif = 3.14159265358979323846f;
        float ang = pif * (float)i;
        ang = ang * (float)(2*j + 1);
        ang = ang / 2048.0f;
        float c = (float)cos((double)ang);
        v = (float)sqrt(2.0/1024.0) * c;
    }
    g_dct[idx] = v;
}

// W_eff = Wqkv, with row blocks [1024:2048) += Wk, [2048:3072) += Wv.
__global__ void add_weights_kernel(const float* __restrict__ Wqkv) {
    int i = blockIdx.x * blockDim.x + threadIdx.x;
    if (i >= QKVC*CC) return;
    float v = Wqkv[i];
    int row = i >> 10;
    if (row >= 2*CC)      v += g_W[CC*CC + i - 2*CC*CC];   // Wv
    else if (row >= CC)   v += g_W[i - CC*CC];             // Wk
    g_Weff[i] = v;
}

// ---------------------------------------------------------------------------
// 3xTF32 tensor-core GEMM, 3-stage cp.async pipeline, single sync/chunk.
// Block tile 128x64x16, 8 warps (warp tile 32x32), mma.sync m16n8k8 tf32.
// fp32-accurate: Dekker mask-split in registers —
//   hi = v & 0xFFFFE000 (exact tf32 truncation, 1 LOP)
//   lo = v - hi         (exact FSUB; HW truncates lo's low mantissa in mma)
// hh accumulates into acc; hl+lh into accL (breaks HMMA RAW chains);
// merged at epilogue. blockIdx.z batching: B += z*zsB, C += z*zsC.
//   TRANSA=0: a(m,k)=A[m*lda+k]   TRANSA=1: a(m,k)=A[k*lda+m]
//   TRANSB=1: b(k,n)=B[n*ldb+k]   TRANSB=0: b(k,n)=B[k*ldb+n]
// M multiple of 128; N multiple of 64; K multiple of 16.

__device__ __forceinline__ void split_mask(float v, unsigned& hi, unsigned& lo) {
    unsigned h = __float_as_uint(v) & 0xFFFFE000u;
    hi = h;
    lo = __float_as_uint(v - __uint_as_float(h));
}

__device__ __forceinline__ void mma8(float* d, const unsigned* a,
                                     unsigned b0, unsigned b1) {
    asm volatile(
        "mma.sync.aligned.m16n8k8.row.col.f32.tf32.tf32.f32 "
        "{%0,%1,%2,%3}, {%4,%5,%6,%7}, {%8,%9}, {%0,%1,%2,%3};\n"
        : "+f"(d[0]), "+f"(d[1]), "+f"(d[2]), "+f"(d[3])
        : "r"(a[0]), "r"(a[1]), "r"(a[2]), "r"(a[3]), "r"(b0), "r"(b1));
}

__device__ __forceinline__ void cp_async16(void* smem_dst, const void* gmem_src) {
    unsigned saddr = (unsigned)__cvta_generic_to_shared(smem_dst);
    asm volatile("cp.async.ca.shared.global [%0], [%1], 16;\n"
                 :: "r"(saddr), "l"(gmem_src));
}
__device__ __forceinline__ void cp_commit() {
    asm volatile("cp.async.commit_group;\n");
}

template<int TRANSA, int TRANSB>
__global__ __launch_bounds__(256, 2)
void mma_gemm3x(int M, int N, int K,
                const float* __restrict__ A, int lda,
                const float* __restrict__ B, int ldb,
                float* __restrict__ C, int ldc,
                size_t zsB, size_t zsC,
                int accumulate, const float* __restrict__ bias) {
    // Raw fp32 tiles, 3 pipeline slots. Row stride 20 -> conflict-free frags.
    __shared__ float Asm[3][128][20];
    __shared__ float Bsm[3][64][20];

    B += (size_t)blockIdx.z * zsB;
    C += (size_t)blockIdx.z * zsC;

    const int t    = threadIdx.x;
    const int lane = t & 31;
    const int wid  = t >> 5;
    const int wr   = wid & 3;          // warp m-index (0..3) -> 32 rows
    const int wc   = wid >> 2;         // warp n-index (0..1) -> 32 cols
    const int m0   = blockIdx.y * 128;
    const int n0   = blockIdx.x * 64;
    const int lg   = lane >> 2;        // 0..7
    const int lt   = lane & 3;         // 0..3

    float acc [2][4][4];   // hi*hi terms
    float accL[2][4][4];   // hi*lo + lo*hi terms (independent RAW chain)
    #pragma unroll
    for (int i = 0; i < 2; i++)
        #pragma unroll
        for (int j = 0; j < 4; j++)
            #pragma unroll
            for (int r = 0; r < 4; r++) { acc[i][j][r] = 0.f; accL[i][j][r] = 0.f; }

    // Stage one 128x16 A tile + 64x16 B tile into slot st.
    auto stage = [&](int st, int k0) {
        if (!TRANSA) {
            #pragma unroll
            for (int it = 0; it < 2; it++) {
                int idx = it * 256 + t;                  // 512 float4
                int m = idx >> 2, kc = (idx & 3) * 4;
                cp_async16(&Asm[st][m][kc],
                           A + (size_t)(m0 + m) * lda + k0 + kc);
            }
        } else {
            #pragma unroll
            for (int it = 0; it < 2; it++) {
                int idx = it * 256 + t;
                int k = idx >> 5, mc = (idx & 31) * 4;
                float4 v = *(const float4*)(A + (size_t)(k0 + k) * lda + m0 + mc);
                Asm[st][mc+0][k] = v.x; Asm[st][mc+1][k] = v.y;
                Asm[st][mc+2][k] = v.z; Asm[st][mc+3][k] = v.w;
            }
        }
        if (TRANSB) {
            int idx = t;                                 // 256 float4
            int n = idx >> 2, kc = (idx & 3) * 4;
            cp_async16(&Bsm[st][n][kc],
                       B + (size_t)(n0 + n) * ldb + k0 + kc);
        } else {
            int idx = t;
            int k = idx >> 4, nc = (idx & 15) * 4;
            float4 v = *(const float4*)(B + (size_t)(k0 + k) * ldb + n0 + nc);
            Bsm[st][nc+0][k] = v.x; Bsm[st][nc+1][k] = v.y;
            Bsm[st][nc+2][k] = v.z; Bsm[st][nc+3][k] = v.w;
        }
        cp_commit();
    };

    const int niter = K >> 4;
    stage(0, 0);
    if (niter > 1) stage(1, 16);

    for (int it = 0; it < niter; it++) {
        const int cur = it % 3;
        if (it + 1 < niter) asm volatile("cp.async.wait_group 1;\n");
        else                asm volatile("cp.async.wait_group 0;\n");
        __syncthreads();   // slot (it-1)%3 free; data of chunk it visible
        if (it + 2 < niter) stage((it + 2) % 3, (it + 2) << 4);

        // ---- compute on slot cur: 2 k-steps of m16n8k8 ----
        #pragma unroll
        for (int ks = 0; ks < 2; ks++) {
            const int c = ks * 8 + lt;
            unsigned ah[2][4], al[2][4];
            #pragma unroll
            for (int ms = 0; ms < 2; ms++) {
                int r = wr * 32 + ms * 16 + lg;
                split_mask(Asm[cur][r    ][c    ], ah[ms][0], al[ms][0]);
                split_mask(Asm[cur][r + 8][c    ], ah[ms][1], al[ms][1]);
                split_mask(Asm[cur][r    ][c + 4], ah[ms][2], al[ms][2]);
                split_mask(Asm[cur][r + 8][c + 4], ah[ms][3], al[ms][3]);
            }
            #pragma unroll
            for (int ns = 0; ns < 4; ns++) {
                int n = wc * 32 + ns * 8 + lg;
                unsigned b0h, b0l, b1h, b1l;
                split_mask(Bsm[cur][n][c    ], b0h, b0l);
                split_mask(Bsm[cur][n][c + 4], b1h, b1l);
                #pragma unroll
                for (int ms = 0; ms < 2; ms++) {
                    mma8(acc [ms][ns], ah[ms], b0h, b1h);  // hi*hi
                    mma8(accL[ms][ns], ah[ms], b0l, b1l);  // hi*lo
                    mma8(accL[ms][ns], al[ms], b0h, b1h);  // lo*hi
                }
            }
        }
    }

    // ---- epilogue (merge hi and lo accumulators) ----
    #pragma unroll
    for (int ms = 0; ms < 2; ms++) {
        #pragma unroll
        for (int ns = 0; ns < 4; ns++) {
            int row = m0 + wr * 32 + ms * 16 + lg;
            int col = n0 + wc * 32 + ns * 8 + 2 * lt;
            float b0 = bias ? bias[col] : 0.f;
            float b1 = bias ? bias[col + 1] : 0.f;
            size_t o0 = (size_t)row * ldc + col;
            size_t o1 = (size_t)(row + 8) * ldc + col;
            float v0 = acc[ms][ns][0] + accL[ms][ns][0] + b0;
            float v1 = acc[ms][ns][1] + accL[ms][ns][1] + b1;
            float v2 = acc[ms][ns][2] + accL[ms][ns][2] + b0;
            float v3 = acc[ms][ns][3] + accL[ms][ns][3] + b1;
            if (accumulate) {
                v0 += C[o0]; v1 += C[o0 + 1];
                v2 += C[o1]; v3 += C[o1 + 1];
            }
            C[o0] = v0; C[o0 + 1] = v1;
            C[o1] = v2; C[o1 + 1] = v3;
        }
    }
}

// ---------------------------------------------------------------------------
// Packed f32x2 helpers (sm_103a FFMA2 — per-lane rounding identical to fmaf)
__device__ __forceinline__ unsigned long long pack2(float lo, float hi) {
    unsigned long long r;
    asm("mov.b64 %0, {%1, %2};" : "=l"(r) : "f"(lo), "f"(hi));
    return r;
}
__device__ __forceinline__ void unpack2(unsigned long long v, float& lo, float& hi) {
    asm("mov.b64 {%0, %1}, %2;" : "=f"(lo), "=f"(hi) : "l"(v));
}
__device__ __forceinline__ void fma2(unsigned long long& d,
                                     unsigned long long a, unsigned long long b) {
    asm("fma.rn.f32x2 %0, %1, %2, %3;" : "=l"(d) : "l"(a), "l"(b), "l"(d));
}
__device__ __forceinline__ void mul2(unsigned long long& d,
                                     unsigned long long a, unsigned long long b) {
    asm("mul.rn.f32x2 %0, %1, %2;" : "=l"(d) : "l"(a), "l"(b));
}

// Flash-style attention (fp32, packed f32x2 math). One block = 64 queries of
// one (b,h); each thread owns one query row.
__global__ __launch_bounds__(64)
void attn_kernel() {
    __shared__ float Ks[64][68];
    __shared__ float Vs[64][68];
    const int tid = threadIdx.x;
    const int bh  = blockIdx.y;
    const int b = bh >> 4, h = bh & 15;
    const int n = blockIdx.x * 64 + tid;

    const float* qrow = g_qkv + (size_t)(b * NN + n) * QKVC + h * HD;
    unsigned long long qv[32];          // 64 dims as 32 pairs (scaled)
    #pragma unroll
    for (int d4 = 0; d4 < 16; d4++) {
        float4 q4 = *(const float4*)(qrow + d4 * 4);
        qv[d4*2+0] = pack2(q4.x * 0.125f, q4.y * 0.125f);
        qv[d4*2+1] = pack2(q4.z * 0.125f, q4.w * 0.125f);
    }

    float m_run = -INFINITY, l_run = 0.f;
    unsigned long long acc[32];
    #pragma unroll
    for (int j = 0; j < 32; j++) acc[j] = 0ull;

    for (int kt = 0; kt < NN / 64; kt++) {
        const float* krow = g_qkv + (size_t)(b * NN + kt * 64 + tid) * QKVC + CC  + h * HD;
        const float* vrow = g_qkv + (size_t)(b * NN + kt * 64 + tid) * QKVC + 2*CC + h * HD;
        #pragma unroll
        for (int d4 = 0; d4 < 16; d4++) {
            *(float4*)&Ks[tid][d4 * 4] = *(const float4*)(krow + d4 * 4);
            *(float4*)&Vs[tid][d4 * 4] = *(const float4*)(vrow + d4 * 4);
        }
        __syncthreads();

        for (int kk = 0; kk < 64; kk++) {
            unsigned long long s2 = 0ull;
            const unsigned long long* k2 = (const unsigned long long*)&Ks[kk][0];
            #pragma unroll
            for (int j = 0; j < 32; j++) fma2(s2, qv[j], k2[j]);
            float slo, shi; unpack2(s2, slo, shi);
            float s = slo + shi;

            if (s > m_run) {
                float corr = expf(m_run - s);   // expf(-inf)=0 handles init
                l_run *= corr;
                unsigned long long c2 = pack2(corr, corr);
                #pragma unroll
                for (int j = 0; j < 32; j++) mul2(acc[j], acc[j], c2);
                m_run = s;
            }
            float p = expf(s - m_run);
            l_run += p;
            unsigned long long p2 = pack2(p, p);
            const unsigned long long* v2 = (const unsigned long long*)&Vs[kk][0];
            #pragma unroll
            for (int j = 0; j < 32; j++) fma2(acc[j], p2, v2[j]);
        }
        __syncthreads();
    }

    float inv = 1.f / l_run;
    float* orow = g_ctx + (size_t)(b * NN + n) * CC + h * HD;
    #pragma unroll
    for (int j = 0; j < 16; j++) {
        float a0, a1, a2, a3;
        unpack2(acc[j*2+0], a0, a1);
        unpack2(acc[j*2+1], a2, a3);
        float4 o4;
        o4.x = a0 * inv; o4.y = a1 * inv;
        o4.z = a2 * inv; o4.w = a3 * inv;
        *(float4*)(orow + j * 4) = o4;
    }
}

// ---------------------------------------------------------------------------
extern "C" void kernel_launch(void* const* d_in, const int* in_sizes, int n_in,
                              void* d_out, int out_size) {
    const float* x     = (const float*)d_in[0];
    const float* Wqkv  = (const float*)d_in[1];
    const float* Wproj = (const float*)d_in[2];
    const float* bproj = (const float*)d_in[3];
    const float* coefk = (const float*)d_in[4];
    const float* coefv = (const float*)d_in[5];
    const int*   indices = (const int*)d_in[6];
    const int*   task  = (const int*)d_in[7];
    float*       out   = (float*)d_out;
    (void)in_sizes; (void)n_in; (void)out_size;

    void *p;
    cudaGetSymbolAddress(&p, g_qkv);  float* qkv  = (float*)p;
    cudaGetSymbolAddress(&p, g_dct);  float* dct  = (float*)p;
    cudaGetSymbolAddress(&p, g_S);    float* S    = (float*)p;
    cudaGetSymbolAddress(&p, g_tmp2); float* tmp2 = (float*)p;
    cudaGetSymbolAddress(&p, g_W);    float* W    = (float*)p;
    cudaGetSymbolAddress(&p, g_Weff); float* Weff = (float*)p;
    cudaGetSymbolAddress(&p, g_ctx);  float* ctx  = (float*)p;

    const size_t PLsz = (size_t)CC * CC;   // one 1024x1024 plane

    // 1. DCT-LoRA weights
    zero_S_kernel<<<(2*CC*CC + 255)/256, 256>>>();
    scatter_kernel<<<(NTASKS*NFRQ + 255)/256, 256>>>(coefk, coefv, indices, task);
    dct_kernel<<<(CC*CC + 255)/256, 256>>>();

    // stage 1 (batched rows): tmp2(2048x1024) = [Sk;Sv] @ Bm
    mma_gemm3x<0,0><<<dim3(16,16,1), 256>>>(
        2*CC, CC, CC, S, CC, dct, CC, tmp2, CC, 0, 0, 0, nullptr);
    // stage 2 (batched z): W{k,v} = Bm^T @ tmp2{k,v}
    mma_gemm3x<1,0><<<dim3(16,8,2), 256>>>(
        CC, CC, CC, dct, CC, tmp2, CC, W, CC, PLsz, PLsz, 0, nullptr);

    // 2. Fuse LoRA weights into qkv weight: W_eff = Wqkv + [0; Wk; Wv]
    add_weights_kernel<<<(QKVC*CC + 255)/256, 256>>>(Wqkv);

    // 3. qkv = x @ W_eff^T  (k/v LoRA adds folded in — one GEMM)
    mma_gemm3x<0,1><<<dim3(QKVC/64, ROWS/128), 256>>>(
        ROWS, QKVC, CC, x, CC, Weff, CC, qkv, QKVC, 0, 0, 0, nullptr);

    // 4. attention -> ctx
    attn_kernel<<<dim3(NN/64, BB*HH), 64>>>();

    // 5. out = ctx @ Wproj^T + b
    mma_gemm3x<0,1><<<dim3(16, ROWS/128), 256>>>(
        ROWS, CC, CC, ctx, CC, Wproj, CC, out, CC, 0, 0, 0, bproj);
}